// round 3
// baseline (speedup 1.0000x reference)
#include <cuda_runtime.h>

#define DIM   2048
#define NVEC  32768          // B*T*N = 2*4096*4
#define VPB   16             // vectors per block
#define NBLK  (NVEC / VPB)   // 2048
#define EPS   1e-6f

__device__ __forceinline__ void facc(float& s, float4 a, float4 b) {
    s = fmaf(a.x, b.x, s);
    s = fmaf(a.y, b.y, s);
    s = fmaf(a.z, b.z, s);
    s = fmaf(a.w, b.w, s);
}

__device__ __forceinline__ float4 mul4(float4 a, float4 b) {
    return make_float4(a.x * b.x, a.y * b.y, a.z * b.z, a.w * b.w);
}

__global__ void __launch_bounds__(256)
hcmaps_kernel(const float* __restrict__ x,
              const float* __restrict__ rmsw,
              const float* __restrict__ alpha_pre,
              const float* __restrict__ alpha_post,
              const float* __restrict__ alpha_res,
              const float* __restrict__ th_pre,
              const float* __restrict__ th_post,
              const float* __restrict__ th_res,
              const float* __restrict__ b_pre,
              const float* __restrict__ b_post,
              const float* __restrict__ b_res,
              float* __restrict__ out)
{
    const int t    = threadIdx.x;
    const int lane = t & 31;
    const int wrp  = t >> 5;
    const int cA   = 4 * t;          // columns cA..cA+3
    const int cB   = 1024 + 4 * t;   // columns cB..cB+3

    // --- Load rms_weight + thetas once per block; fold weight into thetas. ---
    const float4 wA = *(const float4*)(rmsw + cA);
    const float4 wB = *(const float4*)(rmsw + cB);

    const float4 pA  = mul4(*(const float4*)(th_pre  + cA), wA);
    const float4 pB  = mul4(*(const float4*)(th_pre  + cB), wB);
    const float4 qA  = mul4(*(const float4*)(th_post + cA), wA);
    const float4 qB  = mul4(*(const float4*)(th_post + cB), wB);
    const float4 r0A = mul4(*(const float4*)(th_res + 0 * DIM + cA), wA);
    const float4 r0B = mul4(*(const float4*)(th_res + 0 * DIM + cB), wB);
    const float4 r1A = mul4(*(const float4*)(th_res + 1 * DIM + cA), wA);
    const float4 r1B = mul4(*(const float4*)(th_res + 1 * DIM + cB), wB);
    const float4 r2A = mul4(*(const float4*)(th_res + 2 * DIM + cA), wA);
    const float4 r2B = mul4(*(const float4*)(th_res + 2 * DIM + cB), wB);
    const float4 r3A = mul4(*(const float4*)(th_res + 3 * DIM + cA), wA);
    const float4 r3B = mul4(*(const float4*)(th_res + 3 * DIM + cB), wB);

    __shared__ float red[8][7];

    const float apre  = alpha_pre[0];
    const float apost = alpha_post[0];
    const float ares  = alpha_res[0];

    const int v0 = blockIdx.x * VPB;

    for (int vi = 0; vi < VPB; ++vi) {
        const int v = v0 + vi;
        const float4* xv = (const float4*)(x + (size_t)v * DIM);
        const float4 xA = xv[t];         // elems 4t..4t+3
        const float4 xB = xv[256 + t];   // elems 1024+4t..1024+4t+3

        float s[7];
#pragma unroll
        for (int k = 0; k < 7; ++k) s[k] = 0.0f;

        facc(s[0], xA, xA);  facc(s[0], xB, xB);    // sum of squares
        facc(s[1], pA, xA);  facc(s[1], pB, xB);    // theta_pre
        facc(s[2], qA, xA);  facc(s[2], qB, xB);    // theta_post
        facc(s[3], r0A, xA); facc(s[3], r0B, xB);   // theta_res rows
        facc(s[4], r1A, xA); facc(s[4], r1B, xB);
        facc(s[5], r2A, xA); facc(s[5], r2B, xB);
        facc(s[6], r3A, xA); facc(s[6], r3B, xB);

        // warp reduce all 7
#pragma unroll
        for (int k = 0; k < 7; ++k) {
#pragma unroll
            for (int off = 16; off > 0; off >>= 1)
                s[k] += __shfl_xor_sync(0xffffffffu, s[k], off);
        }

        if (lane == 0) {
#pragma unroll
            for (int k = 0; k < 7; ++k) red[wrp][k] = s[k];
        }
        __syncthreads();

        if (t == 0) {
            float tot[7];
#pragma unroll
            for (int k = 0; k < 7; ++k) {
                float a = 0.0f;
#pragma unroll
                for (int w = 0; w < 8; ++w) a += red[w][k];
                tot[k] = a;
            }
            const float scale = rsqrtf(tot[0] * (1.0f / DIM) + EPS);
            const int n  = v & 3;
            const int bt = v >> 2;

            out[v]        = fmaf(apre,  tanhf(tot[1] * scale), b_pre[n]);
            out[NVEC + v] = fmaf(apost, tanhf(tot[2] * scale), b_post[n]);

            float* ores = out + 2 * NVEC + bt * 16 + n;
#pragma unroll
            for (int i = 0; i < 4; ++i)
                ores[4 * i] = fmaf(ares, tanhf(tot[3 + i] * scale), b_res[4 * i + n]);
        }
        __syncthreads();
    }
}

extern "C" void kernel_launch(void* const* d_in, const int* in_sizes, int n_in,
                              void* d_out, int out_size)
{
    const float* x      = (const float*)d_in[0];   // [2,4096,4,2048]
    const float* rmsw   = (const float*)d_in[1];   // [2048]
    const float* apre   = (const float*)d_in[2];   // scalar
    const float* apost  = (const float*)d_in[3];   // scalar
    const float* ares   = (const float*)d_in[4];   // scalar
    const float* tpre   = (const float*)d_in[5];   // [2048]
    const float* tpost  = (const float*)d_in[6];   // [2048]
    const float* tres   = (const float*)d_in[7];   // [4,2048]
    const float* bpre   = (const float*)d_in[8];   // [4]
    const float* bpost  = (const float*)d_in[9];   // [4]
    const float* bres   = (const float*)d_in[10];  // [4,4]
    float* out = (float*)d_out;

    hcmaps_kernel<<<NBLK, 256>>>(x, rmsw, apre, apost, ares,
                                 tpre, tpost, tres, bpre, bpost, bres, out);
}

// round 4
// speedup vs baseline: 1.7817x; 1.7817x over previous
#include <cuda_runtime.h>

#define DIM   2048
#define NVEC  32768          // B*T*N = 2*4096*4
#define VPB   16             // vectors per block
#define NBLK  (NVEC / VPB)   // 2048
#define EPS   1e-6f

__device__ __forceinline__ void facc(float& s, float4 a, float4 b) {
    s = fmaf(a.x, b.x, s);
    s = fmaf(a.y, b.y, s);
    s = fmaf(a.z, b.z, s);
    s = fmaf(a.w, b.w, s);
}

__device__ __forceinline__ float4 mul4(float4 a, float4 b) {
    return make_float4(a.x * b.x, a.y * b.y, a.z * b.z, a.w * b.w);
}

__global__ void __launch_bounds__(256, 3)
hcmaps_kernel(const float* __restrict__ x,
              const float* __restrict__ rmsw,
              const float* __restrict__ alpha_pre,
              const float* __restrict__ alpha_post,
              const float* __restrict__ alpha_res,
              const float* __restrict__ th_pre,
              const float* __restrict__ th_post,
              const float* __restrict__ th_res,
              const float* __restrict__ b_pre,
              const float* __restrict__ b_post,
              const float* __restrict__ b_res,
              float* __restrict__ out)
{
    const int t    = threadIdx.x;
    const int lane = t & 31;
    const int wrp  = t >> 5;
    const int cA   = 4 * t;          // columns cA..cA+3
    const int cB   = 1024 + 4 * t;   // columns cB..cB+3

    // rms_weight folded into thetas once per block (variance uses raw x).
    const float4 wA = *(const float4*)(rmsw + cA);
    const float4 wB = *(const float4*)(rmsw + cB);

    const float4 pA  = mul4(*(const float4*)(th_pre  + cA), wA);
    const float4 pB  = mul4(*(const float4*)(th_pre  + cB), wB);
    const float4 qA  = mul4(*(const float4*)(th_post + cA), wA);
    const float4 qB  = mul4(*(const float4*)(th_post + cB), wB);
    const float4 r0A = mul4(*(const float4*)(th_res + 0 * DIM + cA), wA);
    const float4 r0B = mul4(*(const float4*)(th_res + 0 * DIM + cB), wB);
    const float4 r1A = mul4(*(const float4*)(th_res + 1 * DIM + cA), wA);
    const float4 r1B = mul4(*(const float4*)(th_res + 1 * DIM + cB), wB);
    const float4 r2A = mul4(*(const float4*)(th_res + 2 * DIM + cA), wA);
    const float4 r2B = mul4(*(const float4*)(th_res + 2 * DIM + cB), wB);
    const float4 r3A = mul4(*(const float4*)(th_res + 3 * DIM + cA), wA);
    const float4 r3B = mul4(*(const float4*)(th_res + 3 * DIM + cB), wB);

    // Per-warp partials for all 16 vectors; reduced once at the end.
    __shared__ float part[VPB][7][8];
    __shared__ float tot[VPB][7];

    const int v0 = blockIdx.x * VPB;
    const float4* xbase = (const float4*)(x + (size_t)v0 * DIM);

    // Prime the register double-buffer.
    float4 xA = xbase[t];
    float4 xB = xbase[256 + t];

    for (int vi = 0; vi < VPB; ++vi) {
        // Prefetch next vector before doing any math on the current one.
        float4 nA, nB;
        if (vi + 1 < VPB) {
            const float4* xn = xbase + (size_t)(vi + 1) * (DIM / 4);
            nA = xn[t];
            nB = xn[256 + t];
        }

        float s0 = 0.f, s1 = 0.f, s2 = 0.f, s3 = 0.f,
              s4 = 0.f, s5 = 0.f, s6 = 0.f;

        facc(s0, xA, xA);  facc(s0, xB, xB);    // sum of squares
        facc(s1, pA, xA);  facc(s1, pB, xB);    // theta_pre
        facc(s2, qA, xA);  facc(s2, qB, xB);    // theta_post
        facc(s3, r0A, xA); facc(s3, r0B, xB);   // theta_res rows
        facc(s4, r1A, xA); facc(s4, r1B, xB);
        facc(s5, r2A, xA); facc(s5, r2B, xB);
        facc(s6, r3A, xA); facc(s6, r3B, xB);

        // ---- multi-value warp reduction via transpose (20 SHFL total) ----
        // Round A: sums 0..3
        s0 += __shfl_xor_sync(0xffffffffu, s0, 1);
        s1 += __shfl_xor_sync(0xffffffffu, s1, 1);
        s2 += __shfl_xor_sync(0xffffffffu, s2, 1);
        s3 += __shfl_xor_sync(0xffffffffu, s3, 1);
        s0 += __shfl_xor_sync(0xffffffffu, s0, 2);
        s1 += __shfl_xor_sync(0xffffffffu, s1, 2);
        s2 += __shfl_xor_sync(0xffffffffu, s2, 2);
        s3 += __shfl_xor_sync(0xffffffffu, s3, 2);
        const int sel = lane & 3;
        float vA4 = (sel == 0) ? s0 : (sel == 1) ? s1 : (sel == 2) ? s2 : s3;
        vA4 += __shfl_xor_sync(0xffffffffu, vA4, 4);
        vA4 += __shfl_xor_sync(0xffffffffu, vA4, 8);
        vA4 += __shfl_xor_sync(0xffffffffu, vA4, 16);
        // lane L now holds total of sum (L&3)

        // Round B: sums 4..6
        s4 += __shfl_xor_sync(0xffffffffu, s4, 1);
        s5 += __shfl_xor_sync(0xffffffffu, s5, 1);
        s6 += __shfl_xor_sync(0xffffffffu, s6, 1);
        s4 += __shfl_xor_sync(0xffffffffu, s4, 2);
        s5 += __shfl_xor_sync(0xffffffffu, s5, 2);
        s6 += __shfl_xor_sync(0xffffffffu, s6, 2);
        float vB4 = (sel == 0) ? s4 : (sel == 1) ? s5 : s6;
        vB4 += __shfl_xor_sync(0xffffffffu, vB4, 4);
        vB4 += __shfl_xor_sync(0xffffffffu, vB4, 8);
        vB4 += __shfl_xor_sync(0xffffffffu, vB4, 16);
        // lane L now holds total of sum 4+(L&3) (for L&3 < 3)

        if (lane < 4)      part[vi][lane][wrp] = vA4;
        else if (lane < 7) part[vi][lane][wrp] = vB4;

        xA = nA;
        xB = nB;
    }

    __syncthreads();

    // Phase A: reduce the 8 warp-partials for each (vector, sum).
    if (t < 128) {
        const int v = t >> 3;     // 0..15
        const int k = t & 7;      // 0..7
        if (k < 7) {
            float a = 0.0f;
#pragma unroll
            for (int w = 0; w < 8; ++w) a += part[v][k][w];
            tot[v][k] = a;
        }
    }
    __syncthreads();

    // Phase B: 6 outputs per vector, one thread each (96 threads).
    if (t < 128) {
        const int v = t >> 3;     // local vector 0..15
        const int j = t & 7;      // output slot 0..7 (6 used)
        if (j < 6) {
            const int gv = v0 + v;
            const int n  = gv & 3;
            const int bt = gv >> 2;
            const float scale = rsqrtf(tot[v][0] * (1.0f / DIM) + EPS);
            if (j == 0) {
                out[gv] = fmaf(alpha_pre[0], tanhf(tot[v][1] * scale), b_pre[n]);
            } else if (j == 1) {
                out[NVEC + gv] = fmaf(alpha_post[0], tanhf(tot[v][2] * scale), b_post[n]);
            } else {
                const int i = j - 2;   // residual row 0..3
                out[2 * NVEC + bt * 16 + i * 4 + n] =
                    fmaf(alpha_res[0], tanhf(tot[v][3 + i] * scale), b_res[4 * i + n]);
            }
        }
    }
}

extern "C" void kernel_launch(void* const* d_in, const int* in_sizes, int n_in,
                              void* d_out, int out_size)
{
    const float* x      = (const float*)d_in[0];   // [2,4096,4,2048]
    const float* rmsw   = (const float*)d_in[1];   // [2048]
    const float* apre   = (const float*)d_in[2];   // scalar
    const float* apost  = (const float*)d_in[3];   // scalar
    const float* ares   = (const float*)d_in[4];   // scalar
    const float* tpre   = (const float*)d_in[5];   // [2048]
    const float* tpost  = (const float*)d_in[6];   // [2048]
    const float* tres   = (const float*)d_in[7];   // [4,2048]
    const float* bpre   = (const float*)d_in[8];   // [4]
    const float* bpost  = (const float*)d_in[9];   // [4]
    const float* bres   = (const float*)d_in[10];  // [4,4]
    float* out = (float*)d_out;

    hcmaps_kernel<<<NBLK, 256>>>(x, rmsw, apre, apost, ares,
                                 tpre, tpost, tres, bpre, bpost, bres, out);
}